// round 13
// baseline (speedup 1.0000x reference)
#include <cuda_runtime.h>

#define NIMG 256            // 8 batch * 32 channels

// ---------------- filter banks (db6, pytorch_wavelets conventions) ----------------
__constant__ float c_ana0[12] = {
  0.11154074335008017f, 0.4946238903983854f, 0.7511339080215775f, 0.3152503517092432f,
  -0.22626469396516913f, -0.12976686756709563f, 0.09750160558707936f, 0.02752286553001629f,
  -0.031582039318031156f, 0.0005538422009938016f, 0.004777257511010651f, -0.00107730108499558f };
__constant__ float c_ana1[12] = {
  -0.00107730108499558f, -0.004777257511010651f, 0.0005538422009938016f, 0.031582039318031156f,
  0.02752286553001629f, -0.09750160558707936f, -0.12976686756709563f, 0.22626469396516913f,
  0.3152503517092432f, -0.7511339080215775f, 0.4946238903983854f, -0.11154074335008017f };
__constant__ float c_syn0[12] = {
  -0.00107730108499558f, 0.004777257511010651f, 0.0005538422009938016f, -0.031582039318031156f,
  0.02752286553001629f, 0.09750160558707936f, -0.12976686756709563f, -0.22626469396516913f,
  0.3152503517092432f, 0.7511339080215775f, 0.4946238903983854f, 0.11154074335008017f };
__constant__ float c_syn1[12] = {
  -0.11154074335008017f, 0.4946238903983854f, -0.7511339080215775f, 0.3152503517092432f,
  0.22626469396516913f, -0.12976686756709563f, -0.09750160558707936f, 0.02752286553001629f,
  0.031582039318031156f, 0.0005538422009938016f, -0.004777257511010651f, -0.00107730108499558f };

// ---------------- scratch (device globals) ----------------
__device__ float g_llA [NIMG * 68644];          // 262*262 region (also holds 74-stride data)
__device__ float g_llB [NIMG * 18496];          // 136*136
__device__ float g_yh1 [NIMG * 3 * 68644];      // rst 262, sb 68644
__device__ float g_yh2 [NIMG * 3 * 18496];      // rst 136, sb 18496
__device__ float g_yh3 [NIMG * 3 * 5476];       // rst 74,  sb 5476
__device__ float g_yh4 [NIMG * 3 * 1764];       // rst 42,  sb 1764
__device__ float g_yl4 [NIMG * 1764];
__device__ float g_yl4t[NIMG * 1764];
__device__ float g_yh4t[NIMG * 3 * 1764];

__device__ __forceinline__ int refl(int j, int N) {
    j = (j < 0) ? (-1 - j) : j;
    j = (j >= N) ? (2 * N - 1 - j) : j;
    return j;
}

// ============ fused forward level: input (WIN x WIN) -> 4 subbands (WOUT x WOUT) ============
// One block: 32x32 output tile. smem: input tile (2*32+12)^2, lo/hi intermediates.
template<int WIN, int IN_RST, int IN_IST, int WOUT, int O_RST,
         int LL_IST, int YH_IST, int SB>
__global__ void __launch_bounds__(256)
k_fwd(const float* __restrict__ in, float* __restrict__ ll, float* __restrict__ yh)
{
    constexpr int T  = 32;
    constexpr int IR = 2 * T + 12;     // 76
    __shared__ float s_in[IR][IR + 1];
    __shared__ float s_lo[IR][T + 1];
    __shared__ float s_hi[IR][T + 1];
    int img  = blockIdx.z;
    int row0 = blockIdx.y * T;
    int col0 = blockIdx.x * T;
    int tid  = threadIdx.x;
    const float* base = in + (size_t)img * IN_IST;
    int jr0 = 2 * row0 - 10, jc0 = 2 * col0 - 10;

    // stage 1: load input tile with symmetric reflection
    for (int i = tid; i < IR * IR; i += 256) {
        int rr = i / IR, cc = i % IR;
        s_in[rr][cc] = base[(size_t)refl(jr0 + rr, WIN) * IN_RST + refl(jc0 + cc, WIN)];
    }
    __syncthreads();

    // stage 2: row filter (pairs of output columns share 14-tap window)
    for (int i = tid; i < IR * (T / 2); i += 256) {
        int rr = i / (T / 2), tp = i % (T / 2);
        int c4 = 4 * tp;
        float a0 = 0.f, a1 = 0.f, b0 = 0.f, b1 = 0.f;
#pragma unroll
        for (int k = 0; k < 12; k++) {
            float v0 = s_in[rr][c4 + k];
            float v1 = s_in[rr][c4 + 2 + k];
            a0 = fmaf(v0, c_ana0[k], a0); a1 = fmaf(v0, c_ana1[k], a1);
            b0 = fmaf(v1, c_ana0[k], b0); b1 = fmaf(v1, c_ana1[k], b1);
        }
        s_lo[rr][2 * tp] = a0; s_lo[rr][2 * tp + 1] = b0;
        s_hi[rr][2 * tp] = a1; s_hi[rr][2 * tp + 1] = b1;
    }
    __syncthreads();

    // stage 3: col filter (pairs of output rows), write 4 subbands
    float* pll = ll + (size_t)img * LL_IST;
    float* pyh = yh + (size_t)img * YH_IST;
    for (int i = tid; i < (T / 2) * T; i += 256) {
        int q  = i / T, tc = i % T;
        int r4 = 4 * q;
        float ll0=0,lh0=0,hl0=0,hh0=0, ll1=0,lh1=0,hl1=0,hh1=0;
#pragma unroll
        for (int k = 0; k < 12; k++) {
            float l0 = s_lo[r4 + k][tc],     h0 = s_hi[r4 + k][tc];
            float l1 = s_lo[r4 + 2 + k][tc], h1 = s_hi[r4 + 2 + k][tc];
            ll0 = fmaf(l0, c_ana0[k], ll0); lh0 = fmaf(l0, c_ana1[k], lh0);
            hl0 = fmaf(h0, c_ana0[k], hl0); hh0 = fmaf(h0, c_ana1[k], hh0);
            ll1 = fmaf(l1, c_ana0[k], ll1); lh1 = fmaf(l1, c_ana1[k], lh1);
            hl1 = fmaf(h1, c_ana0[k], hl1); hh1 = fmaf(h1, c_ana1[k], hh1);
        }
        int or0 = row0 + 2 * q, oc = col0 + tc;
        if (oc < WOUT) {
            if (or0 < WOUT) {
                size_t p = (size_t)or0 * O_RST + oc;
                pll[p] = ll0; pyh[p] = lh0; pyh[SB + p] = hl0; pyh[2 * SB + p] = hh0;
            }
            if (or0 + 1 < WOUT) {
                size_t p = (size_t)(or0 + 1) * O_RST + oc;
                pll[p] = ll1; pyh[p] = lh1; pyh[SB + p] = hl1; pyh[2 * SB + p] = hh1;
            }
        }
    }
}

// ============ fused inverse level: 4 subbands (N x N) -> output (HOUT x HOUT) ============
// One block: 32x64 output tile. Reads clamped to N-1 (clamped values only feed guarded stores).
template<int N, int RST, int LL_IST, int YH_IST, int SB,
         int HOUT, int O_RST, int O_IST>
__global__ void __launch_bounds__(256)
k_inv(const float* __restrict__ ll, const float* __restrict__ yh, float* __restrict__ out)
{
    constexpr int TH = 32, TW = 64;
    constexpr int SR = TH / 2 + 6;    // 22
    constexpr int SC = TW / 2 + 6;    // 38
    __shared__ float s_ll[SR][SC + 1], s_lh[SR][SC + 1], s_hl[SR][SC + 1], s_hh[SR][SC + 1];
    __shared__ float s_lo[TH][SC + 1], s_hi[TH][SC + 1];
    int img  = blockIdx.z;
    int row0 = blockIdx.y * TH;
    int col0 = blockIdx.x * TW;
    int tid  = threadIdx.x;
    int m0 = row0 / 2, u0 = col0 / 2;
    const float* pll = ll + (size_t)img * LL_IST;
    const float* pyh = yh + (size_t)img * YH_IST;

    // stage 1: load 4 subband tiles (index-clamped)
    for (int i = tid; i < SR * SC; i += 256) {
        int rr = i / SC, cc = i % SC;
        int m = min(m0 + rr, N - 1), u = min(u0 + cc, N - 1);
        size_t p = (size_t)m * RST + u;
        s_ll[rr][cc] = pll[p];
        s_lh[rr][cc] = pyh[p];
        s_hl[rr][cc] = pyh[SB + p];
        s_hh[rr][cc] = pyh[2 * SB + p];
    }
    __syncthreads();

    // stage 2: column synthesis (row-pairs share the 6 subband rows)
    for (int i = tid; i < (TH / 2) * SC; i += 256) {
        int q = i / SC, u = i % SC;
        float e_lo=0,o_lo=0,e_hi=0,o_hi=0;
#pragma unroll
        for (int dm = 0; dm < 6; dm++) {
            float a = s_ll[q + dm][u], b = s_lh[q + dm][u];
            float c = s_hl[q + dm][u], d = s_hh[q + dm][u];
            float s0e = c_syn0[1 + 2*dm], s1e = c_syn1[1 + 2*dm];
            float s0o = c_syn0[2*dm],     s1o = c_syn1[2*dm];
            e_lo = fmaf(a, s0e, e_lo); e_lo = fmaf(b, s1e, e_lo);
            o_lo = fmaf(a, s0o, o_lo); o_lo = fmaf(b, s1o, o_lo);
            e_hi = fmaf(c, s0e, e_hi); e_hi = fmaf(d, s1e, e_hi);
            o_hi = fmaf(c, s0o, o_hi); o_hi = fmaf(d, s1o, o_hi);
        }
        s_lo[2 * q][u] = e_lo; s_lo[2 * q + 1][u] = o_lo;
        s_hi[2 * q][u] = e_hi; s_hi[2 * q + 1][u] = o_hi;
    }
    __syncthreads();

    // stage 3: row synthesis (col-pairs), float2 stores
    float* po = out + (size_t)img * O_IST;
    for (int i = tid; i < TH * (TW / 2); i += 256) {
        int y = i / (TW / 2), xp = i % (TW / 2);
        float e = 0.f, o = 0.f;
#pragma unroll
        for (int dm = 0; dm < 6; dm++) {
            float a = s_lo[y][xp + dm], b = s_hi[y][xp + dm];
            e = fmaf(a, c_syn0[1 + 2*dm], e); e = fmaf(b, c_syn1[1 + 2*dm], e);
            o = fmaf(a, c_syn0[2*dm],     o); o = fmaf(b, c_syn1[2*dm],     o);
        }
        int yg = row0 + y, xg = col0 + 2 * xp;
        if (yg < HOUT && xg < HOUT)   // HOUT even, xg even -> pair fully in range
            *reinterpret_cast<float2*>(po + (size_t)yg * O_RST + xg) = make_float2(e, o);
    }
}

// ---------- per-pixel channel mixing at the coarsest scale ----------
__global__ void __launch_bounds__(256)
k_mix_yl(const float* __restrict__ in, const float* __restrict__ w, float* __restrict__ out)
{
    int idx = blockIdx.x * 256 + threadIdx.x;
    if (idx >= 8 * 32 * 1764) return;
    int p = idx % 1764;
    int o = (idx / 1764) % 32;
    int bB = idx / (1764 * 32);
    float acc = 0.f;
#pragma unroll
    for (int i = 0; i < 32; i++)
        acc = fmaf(in[(bB * 32 + i) * 1764 + p], w[(i * 32 + o) * 1764 + p], acc);
    out[idx] = acc;
}

__global__ void __launch_bounds__(256)
k_mix_yh(const float* __restrict__ in, const float* __restrict__ w, float* __restrict__ out)
{
    int idx = blockIdx.x * 256 + threadIdx.x;
    if (idx >= 8 * 32 * 3 * 1764) return;
    int p = idx % 1764;
    int c = (idx / 1764) % 3;
    int o = (idx / (1764 * 3)) % 32;
    int bB = idx / (1764 * 3 * 32);
    float acc = 0.f;
#pragma unroll
    for (int i = 0; i < 32; i++)
        acc = fmaf(in[((bB * 32 + i) * 3 + c) * 1764 + p],
                   w [((i * 32 + o) * 3 + c) * 1764 + p], acc);
    out[idx] = acc;
}

static inline int grd1(long n) { return (int)((n + 255) / 256); }
static inline int tiles(int n, int t) { return (n + t - 1) / t; }

extern "C" void kernel_launch(void* const* d_in, const int* in_sizes, int n_in,
                              void* d_out, int out_size)
{
    const float* x    = (const float*)d_in[0];
    const float* w_yl = (const float*)d_in[1];
    const float* w_yh = (const float*)d_in[2];
    float* out = (float*)d_out;

    float *llA, *llB, *yh1, *yh2, *yh3, *yl4, *yh4, *yl4t, *yh4t;
    cudaGetSymbolAddress((void**)&llA,  g_llA);
    cudaGetSymbolAddress((void**)&llB,  g_llB);
    cudaGetSymbolAddress((void**)&yh1,  g_yh1);
    cudaGetSymbolAddress((void**)&yh2,  g_yh2);
    cudaGetSymbolAddress((void**)&yh3,  g_yh3);
    cudaGetSymbolAddress((void**)&yl4,  g_yl4);
    cudaGetSymbolAddress((void**)&yh4,  g_yh4);
    cudaGetSymbolAddress((void**)&yl4t, g_yl4t);
    cudaGetSymbolAddress((void**)&yh4t, g_yh4t);

    // ================= forward DWT (one fused kernel per level) =================
    // L1: x 512x512 -> subbands 261 (rst 262)
    k_fwd<512,512,262144, 261,262, 68644, 3*68644, 68644>
        <<<dim3(tiles(261,32), tiles(261,32), NIMG), 256>>>(x, llA, yh1);
    // L2: llA 261 (rst 262) -> 136 (rst 136)
    k_fwd<261,262,68644, 136,136, 18496, 3*18496, 18496>
        <<<dim3(tiles(136,32), tiles(136,32), NIMG), 256>>>(llA, llB, yh2);
    // L3: llB 136 -> 73 (rst 74); ll into llA region
    k_fwd<136,136,18496, 73,74, 68644, 3*5476, 5476>
        <<<dim3(tiles(73,32), tiles(73,32), NIMG), 256>>>(llB, llA, yh3);
    // L4: llA 73 (rst 74) -> 42 (rst 42)
    k_fwd<73,74,68644, 42,42, 1764, 3*1764, 1764>
        <<<dim3(tiles(42,32), tiles(42,32), NIMG), 256>>>(llA, yl4, yh4);

    // ================= channel mixing =================
    k_mix_yl<<<grd1(8L*32*1764),   256>>>(yl4, w_yl, yl4t);
    k_mix_yh<<<grd1(8L*32*3*1764), 256>>>(yh4, w_yh, yh4t);

    // ================= inverse DWT (one fused kernel per level) =================
    // L4: subbands 42 -> 74x74 into llA (rst 74)
    k_inv<42,42, 1764, 3*1764, 1764, 74, 74, 68644>
        <<<dim3(tiles(74,64), tiles(74,32), NIMG), 256>>>(yl4t, yh4t, llA);
    // L3: ll=llA cropped to 73 (rst 74) + yh3 -> 136x136 into llB
    k_inv<73,74, 68644, 3*5476, 5476, 136, 136, 18496>
        <<<dim3(tiles(136,64), tiles(136,32), NIMG), 256>>>(llA, yh3, llB);
    // L2: ll=llB 136 + yh2 -> 262x262 into llA (rst 262)
    k_inv<136,136, 18496, 3*18496, 18496, 262, 262, 68644>
        <<<dim3(tiles(262,64), tiles(262,32), NIMG), 256>>>(llB, yh2, llA);
    // L1: ll=llA cropped to 261 (rst 262) + yh1 -> 512x512 into d_out
    k_inv<261,262, 68644, 3*68644, 68644, 512, 512, 262144>
        <<<dim3(tiles(512,64), tiles(512,32), NIMG), 256>>>(llA, yh1, out);
}

// round 14
// speedup vs baseline: 1.0332x; 1.0332x over previous
#include <cuda_runtime.h>

#define NIMG 256            // 8 batch * 32 channels

// ---------------- filter banks (db6, pytorch_wavelets conventions) ----------------
__constant__ float c_ana0[12] = {
  0.11154074335008017f, 0.4946238903983854f, 0.7511339080215775f, 0.3152503517092432f,
  -0.22626469396516913f, -0.12976686756709563f, 0.09750160558707936f, 0.02752286553001629f,
  -0.031582039318031156f, 0.0005538422009938016f, 0.004777257511010651f, -0.00107730108499558f };
__constant__ float c_ana1[12] = {
  -0.00107730108499558f, -0.004777257511010651f, 0.0005538422009938016f, 0.031582039318031156f,
  0.02752286553001629f, -0.09750160558707936f, -0.12976686756709563f, 0.22626469396516913f,
  0.3152503517092432f, -0.7511339080215775f, 0.4946238903983854f, -0.11154074335008017f };
__constant__ float c_syn0[12] = {
  -0.00107730108499558f, 0.004777257511010651f, 0.0005538422009938016f, -0.031582039318031156f,
  0.02752286553001629f, 0.09750160558707936f, -0.12976686756709563f, -0.22626469396516913f,
  0.3152503517092432f, 0.7511339080215775f, 0.4946238903983854f, 0.11154074335008017f };
__constant__ float c_syn1[12] = {
  -0.11154074335008017f, 0.4946238903983854f, -0.7511339080215775f, 0.3152503517092432f,
  0.22626469396516913f, -0.12976686756709563f, -0.09750160558707936f, 0.02752286553001629f,
  0.031582039318031156f, 0.0005538422009938016f, -0.004777257511010651f, -0.00107730108499558f };

// ---------------- scratch (device globals; even row strides everywhere) ----------------
__device__ float g_tmpA[NIMG * 512 * 262];
__device__ float g_tmpB[NIMG * 512 * 262];
__device__ float g_llA [NIMG * 68644];          // 262*262
__device__ float g_llB [NIMG * 18496];          // 136*136
__device__ float g_yh1 [NIMG * 3 * 68644];      // rst 262, sb 68644
__device__ float g_yh2 [NIMG * 3 * 18496];      // rst 136
__device__ float g_yh3 [NIMG * 3 * 5476];       // rst 74,  sb 5476
__device__ float g_yh4 [NIMG * 3 * 1764];       // rst 42
__device__ float g_yl4 [NIMG * 1764];
__device__ float g_yl4t[NIMG * 1764];
__device__ float g_yh4t[NIMG * 3 * 1764];

__device__ __forceinline__ int refl(int j, int N) {
    j = (j < 0) ? (-1 - j) : j;
    j = (j >= N) ? (2 * N - 1 - j) : j;
    return j;
}

// ---------- analysis along width, smem row-band staging ----------
// in (NIMG, H, WIN) -> lo,hi (NIMG, H, WOUT) with row stride O_RST
template<int H, int WIN, int WOUT, int IN_IST, int IN_RST, int O_RST, int O_IST, int RPB>
__global__ void __launch_bounds__(256)
k_afb_rows(const float* __restrict__ in, float* __restrict__ lo, float* __restrict__ hi)
{
    constexpr int NP = (WOUT + 1) / 2;
    __shared__ float s[RPB][WIN + 1];
    int img = blockIdx.y;
    int r0  = blockIdx.x * RPB;
    int tid = threadIdx.x;
    int rmax = min(RPB, H - r0);
    const float* base = in + (size_t)img * IN_IST + (size_t)r0 * IN_RST;
    for (int i = tid; i < rmax * WIN; i += 256) {
        int rr = i / WIN, cc = i % WIN;
        s[rr][cc] = base[(size_t)rr * IN_RST + cc];
    }
    __syncthreads();
    for (int i = tid; i < rmax * NP; i += 256) {
        int rr = i / NP, pi = i % NP;
        int j0 = 4 * pi - 10;
        float w[14];
        if (j0 >= 0 && j0 + 13 < WIN) {
#pragma unroll
            for (int k = 0; k < 14; k++) w[k] = s[rr][j0 + k];
        } else {
#pragma unroll
            for (int k = 0; k < 14; k++) w[k] = s[rr][refl(j0 + k, WIN)];
        }
        float a0 = 0.f, a1 = 0.f, b0 = 0.f, b1 = 0.f;
#pragma unroll
        for (int k = 0; k < 12; k++) {
            a0 = fmaf(w[k],     c_ana0[k], a0);
            a1 = fmaf(w[k],     c_ana1[k], a1);
            b0 = fmaf(w[k + 2], c_ana0[k], b0);
            b1 = fmaf(w[k + 2], c_ana1[k], b1);
        }
        int t0 = 2 * pi, r = r0 + rr;
        float* plo = lo + (size_t)img * O_IST + (size_t)r * O_RST + t0;
        float* phi = hi + (size_t)img * O_IST + (size_t)r * O_RST + t0;
        *reinterpret_cast<float2*>(plo) = make_float2(a0, b0);  // WOUT odd -> pad col
        *reinterpret_cast<float2*>(phi) = make_float2(a1, b1);
    }
}

// ---------- analysis along height, row-pair + col-pair threads (unchanged, R12) ----------
template<int HIN, int W, int IN_IST, int IN_RST, int HOUT,
         int LO_IST, int HI_IST, int O_RST>
__global__ void __launch_bounds__(256)
k_afb_cols(const float* __restrict__ in, float* __restrict__ lo, float* __restrict__ hi)
{
    constexpr int HP = (HOUT + 1) / 2;
    constexpr int WP = (W + 1) / 2;
    int idx = blockIdx.x * 256 + threadIdx.x;
    if (idx >= HP * WP) return;
    int ci = idx % WP;
    int pi = idx / WP;
    int img = blockIdx.y;
    int c2 = 2 * ci;
    int t0 = 2 * pi;
    const float* im = in + (size_t)img * IN_IST + c2;
    int j0 = 2 * t0 - 10;
    float l0x=0,l0y=0,l1x=0,l1y=0,h0x=0,h0y=0,h1x=0,h1y=0;
    if (j0 >= 0 && j0 + 13 < HIN) {
        const float* p = im + (size_t)j0 * IN_RST;
#pragma unroll
        for (int k = 0; k < 14; k++) {
            float2 v = *reinterpret_cast<const float2*>(p + (size_t)k * IN_RST);
            if (k < 12) {
                l0x = fmaf(v.x, c_ana0[k], l0x); l0y = fmaf(v.y, c_ana0[k], l0y);
                h0x = fmaf(v.x, c_ana1[k], h0x); h0y = fmaf(v.y, c_ana1[k], h0y);
            }
            if (k >= 2) {
                l1x = fmaf(v.x, c_ana0[k-2], l1x); l1y = fmaf(v.y, c_ana0[k-2], l1y);
                h1x = fmaf(v.x, c_ana1[k-2], h1x); h1y = fmaf(v.y, c_ana1[k-2], h1y);
            }
        }
    } else {
#pragma unroll
        for (int k = 0; k < 14; k++) {
            int jr = refl(j0 + k, HIN);
            float2 v = *reinterpret_cast<const float2*>(im + (size_t)jr * IN_RST);
            if (k < 12) {
                l0x = fmaf(v.x, c_ana0[k], l0x); l0y = fmaf(v.y, c_ana0[k], l0y);
                h0x = fmaf(v.x, c_ana1[k], h0x); h0y = fmaf(v.y, c_ana1[k], h0y);
            }
            if (k >= 2) {
                l1x = fmaf(v.x, c_ana0[k-2], l1x); l1y = fmaf(v.y, c_ana0[k-2], l1y);
                h1x = fmaf(v.x, c_ana1[k-2], h1x); h1y = fmaf(v.y, c_ana1[k-2], h1y);
            }
        }
    }
    float* plo = lo + (size_t)img * LO_IST + (size_t)t0 * O_RST + c2;
    float* phi = hi + (size_t)img * HI_IST + (size_t)t0 * O_RST + c2;
    *reinterpret_cast<float2*>(plo)          = make_float2(l0x, l0y);
    *reinterpret_cast<float2*>(plo + O_RST)  = make_float2(l1x, l1y);
    *reinterpret_cast<float2*>(phi)          = make_float2(h0x, h0y);
    *reinterpret_cast<float2*>(phi + O_RST)  = make_float2(h1x, h1y);
}

// ---------- synthesis along height: row-pair + float2 cols (unchanged, R12) ----------
template<int N, int W, int A_IST, int A_RST, int B_IST, int B_RST, int O_IST, int O_RST>
__global__ void __launch_bounds__(256)
k_sfb_cols(const float* __restrict__ a, const float* __restrict__ b, float* __restrict__ out)
{
    constexpr int NP = N - 5;
    constexpr int WP = (W + 1) / 2;
    int idx = blockIdx.x * 256 + threadIdx.x;
    if (idx >= NP * WP) return;
    int ci = idx % WP;
    int u  = idx / WP;
    int img = blockIdx.y;
    int c2 = 2 * ci;
    const float* pa = a + (size_t)img * A_IST + (size_t)u * A_RST + c2;
    const float* pb = b + (size_t)img * B_IST + (size_t)u * B_RST + c2;
    float ex=0,ey=0,ox=0,oy=0;
#pragma unroll
    for (int dm = 0; dm < 6; dm++) {
        float2 va = *reinterpret_cast<const float2*>(pa + (size_t)dm * A_RST);
        float2 vb = *reinterpret_cast<const float2*>(pb + (size_t)dm * B_RST);
        float s0e = c_syn0[1 + 2*dm], s1e = c_syn1[1 + 2*dm];
        float s0o = c_syn0[2*dm],     s1o = c_syn1[2*dm];
        ex = fmaf(va.x, s0e, ex); ey = fmaf(va.y, s0e, ey);
        ex = fmaf(vb.x, s1e, ex); ey = fmaf(vb.y, s1e, ey);
        ox = fmaf(va.x, s0o, ox); oy = fmaf(va.y, s0o, oy);
        ox = fmaf(vb.x, s1o, ox); oy = fmaf(vb.y, s1o, oy);
    }
    float* po = out + (size_t)img * O_IST + (size_t)(2 * u) * O_RST + c2;
    *reinterpret_cast<float2*>(po)         = make_float2(ex, ey);
    *reinterpret_cast<float2*>(po + O_RST) = make_float2(ox, oy);
}

// ---------- synthesis along width, smem row-band staging, output quads ----------
// a,b (NIMG, H, N stride RST) -> out (NIMG, H, NOUT stride O_RST)
template<int H, int N, int A_IST, int A_RST, int B_IST, int B_RST,
         int NOUT, int O_IST, int O_RST, int RPB>
__global__ void __launch_bounds__(256)
k_sfb_rows(const float* __restrict__ a, const float* __restrict__ b, float* __restrict__ out)
{
    constexpr int NQ = (NOUT + 3) / 4;
    __shared__ float sa[RPB][N + 2];
    __shared__ float sb[RPB][N + 2];
    int img = blockIdx.y;
    int r0  = blockIdx.x * RPB;
    int tid = threadIdx.x;
    int rmax = min(RPB, H - r0);
    const float* pa = a + (size_t)img * A_IST + (size_t)r0 * A_RST;
    const float* pb = b + (size_t)img * B_IST + (size_t)r0 * B_RST;
    for (int i = tid; i < rmax * N; i += 256) {
        int rr = i / N, cc = i % N;
        sa[rr][cc] = pa[(size_t)rr * A_RST + cc];
        sb[rr][cc] = pb[(size_t)rr * B_RST + cc];
    }
    for (int i = tid; i < rmax * 2; i += 256) {     // zero-pad margin taps
        int rr = i / 2, cc = N + (i % 2);
        sa[rr][cc] = 0.f; sb[rr][cc] = 0.f;
    }
    __syncthreads();
    for (int i = tid; i < rmax * NQ; i += 256) {
        int rr = i / NQ, q = i % NQ;
        float o0=0,o1=0,o2=0,o3=0;
#pragma unroll
        for (int dm = 0; dm < 6; dm++) {
            float wa0 = sa[rr][2*q + dm],     wb0 = sb[rr][2*q + dm];
            float wa1 = sa[rr][2*q + dm + 1], wb1 = sb[rr][2*q + dm + 1];
            float s0e = c_syn0[1 + 2*dm], s1e = c_syn1[1 + 2*dm];
            float s0o = c_syn0[2*dm],     s1o = c_syn1[2*dm];
            o0 = fmaf(wa0, s0e, o0); o0 = fmaf(wb0, s1e, o0);
            o1 = fmaf(wa0, s0o, o1); o1 = fmaf(wb0, s1o, o1);
            o2 = fmaf(wa1, s0e, o2); o2 = fmaf(wb1, s1e, o2);
            o3 = fmaf(wa1, s0o, o3); o3 = fmaf(wb1, s1o, o3);
        }
        int r = r0 + rr;
        float* po = out + (size_t)img * O_IST + (size_t)r * O_RST + 4 * q;
        if (4 * q + 3 < NOUT) {
            *reinterpret_cast<float2*>(po)     = make_float2(o0, o1);
            *reinterpret_cast<float2*>(po + 2) = make_float2(o2, o3);
        } else {
            if (4 * q     < NOUT) po[0] = o0;
            if (4 * q + 1 < NOUT) po[1] = o1;
            if (4 * q + 2 < NOUT) po[2] = o2;
            if (4 * q + 3 < NOUT) po[3] = o3;
        }
    }
}

// ---------- per-pixel channel mixing at the coarsest scale ----------
__global__ void __launch_bounds__(256)
k_mix_yl(const float* __restrict__ in, const float* __restrict__ w, float* __restrict__ out)
{
    int idx = blockIdx.x * 256 + threadIdx.x;
    if (idx >= 8 * 32 * 1764) return;
    int p = idx % 1764;
    int o = (idx / 1764) % 32;
    int bB = idx / (1764 * 32);
    float acc = 0.f;
#pragma unroll
    for (int i = 0; i < 32; i++)
        acc = fmaf(in[(bB * 32 + i) * 1764 + p], w[(i * 32 + o) * 1764 + p], acc);
    out[idx] = acc;
}

__global__ void __launch_bounds__(256)
k_mix_yh(const float* __restrict__ in, const float* __restrict__ w, float* __restrict__ out)
{
    int idx = blockIdx.x * 256 + threadIdx.x;
    if (idx >= 8 * 32 * 3 * 1764) return;
    int p = idx % 1764;
    int c = (idx / 1764) % 3;
    int o = (idx / (1764 * 3)) % 32;
    int bB = idx / (1764 * 3 * 32);
    float acc = 0.f;
#pragma unroll
    for (int i = 0; i < 32; i++)
        acc = fmaf(in[((bB * 32 + i) * 3 + c) * 1764 + p],
                   w [((i * 32 + o) * 3 + c) * 1764 + p], acc);
    out[idx] = acc;
}

static inline dim3 grd2(long n) { return dim3((unsigned)((n + 255) / 256), NIMG, 1); }
static inline dim3 grdR(int h, int rpb) { return dim3((unsigned)((h + rpb - 1) / rpb), NIMG, 1); }
static inline int  grd1(long n) { return (int)((n + 255) / 256); }

extern "C" void kernel_launch(void* const* d_in, const int* in_sizes, int n_in,
                              void* d_out, int out_size)
{
    const float* x    = (const float*)d_in[0];
    const float* w_yl = (const float*)d_in[1];
    const float* w_yh = (const float*)d_in[2];
    float* out = (float*)d_out;

    float *tmpA, *tmpB, *llA, *llB, *yh1, *yh2, *yh3, *yl4, *yh4, *yl4t, *yh4t;
    cudaGetSymbolAddress((void**)&tmpA, g_tmpA);
    cudaGetSymbolAddress((void**)&tmpB, g_tmpB);
    cudaGetSymbolAddress((void**)&llA,  g_llA);
    cudaGetSymbolAddress((void**)&llB,  g_llB);
    cudaGetSymbolAddress((void**)&yh1,  g_yh1);
    cudaGetSymbolAddress((void**)&yh2,  g_yh2);
    cudaGetSymbolAddress((void**)&yh3,  g_yh3);
    cudaGetSymbolAddress((void**)&yl4,  g_yl4);
    cudaGetSymbolAddress((void**)&yh4,  g_yh4);
    cudaGetSymbolAddress((void**)&yl4t, g_yl4t);
    cudaGetSymbolAddress((void**)&yh4t, g_yh4t);

    // ================= forward DWT =================
    // level 1: 512x512 -> 261x261 (ll rst 262)
    k_afb_rows<512,512,261, 512*512,512, 262, 512*262, 4><<<grdR(512,4),256>>>(x, tmpA, tmpB);
    k_afb_cols<512,261, 512*262,262, 261, 68644, 3*68644, 262><<<grd2(131L*131),256>>>(tmpA, llA, yh1);
    k_afb_cols<512,261, 512*262,262, 261, 3*68644, 3*68644, 262><<<grd2(131L*131),256>>>(tmpB, yh1+68644, yh1+2*68644);
    // level 2: 261 -> 136
    k_afb_rows<261,261,136, 68644,262, 136, 262*136, 4><<<grdR(261,4),256>>>(llA, tmpA, tmpB);
    k_afb_cols<261,136, 262*136,136, 136, 18496, 3*18496, 136><<<grd2(68L*68),256>>>(tmpA, llB, yh2);
    k_afb_cols<261,136, 262*136,136, 136, 3*18496, 3*18496, 136><<<grd2(68L*68),256>>>(tmpB, yh2+18496, yh2+2*18496);
    // level 3: 136 -> 73 (rst 74)
    k_afb_rows<136,136,73, 18496,136, 74, 137*74, 8><<<grdR(136,8),256>>>(llB, tmpA, tmpB);
    k_afb_cols<136,73, 137*74,74, 73, 5476, 3*5476, 74><<<grd2(37L*37),256>>>(tmpA, llA, yh3);
    k_afb_cols<136,73, 137*74,74, 73, 3*5476, 3*5476, 74><<<grd2(37L*37),256>>>(tmpB, yh3+5476, yh3+2*5476);
    // level 4: 73 -> 42
    k_afb_rows<73,73,42, 5476,74, 42, 75*42, 12><<<grdR(73,12),256>>>(llA, tmpA, tmpB);
    k_afb_cols<73,42, 75*42,42, 42, 1764, 3*1764, 42><<<grd2(21L*21),256>>>(tmpA, yl4, yh4);
    k_afb_cols<73,42, 75*42,42, 42, 3*1764, 3*1764, 42><<<grd2(21L*21),256>>>(tmpB, yh4+1764, yh4+2*1764);

    // ================= channel mixing =================
    k_mix_yl<<<grd1(8L*32*1764),   256>>>(yl4, w_yl, yl4t);
    k_mix_yh<<<grd1(8L*32*3*1764), 256>>>(yh4, w_yh, yh4t);

    // ================= inverse DWT =================
    // level 4: 42 -> 74x74
    k_sfb_cols<42,42, 1764,42, 3*1764,42, 75*42,42><<<grd2(37L*21),256>>>(yl4t,      yh4t,        tmpA);
    k_sfb_cols<42,42, 3*1764,42, 3*1764,42, 75*42,42><<<grd2(37L*21),256>>>(yh4t+1764, yh4t+2*1764, tmpB);
    k_sfb_rows<74,42, 75*42,42, 75*42,42, 74, 5476,74, 12><<<grdR(74,12),256>>>(tmpA, tmpB, llA);
    // level 3: crop 74->73 -> 136x136
    k_sfb_cols<73,73, 5476,74, 3*5476,74, 137*74,74><<<grd2(68L*37),256>>>(llA,      yh3,        tmpA);
    k_sfb_cols<73,73, 3*5476,74, 3*5476,74, 137*74,74><<<grd2(68L*37),256>>>(yh3+5476, yh3+2*5476, tmpB);
    k_sfb_rows<136,73, 137*74,74, 137*74,74, 136, 18496,136, 8><<<grdR(136,8),256>>>(tmpA, tmpB, llB);
    // level 2: 136 -> 262x262
    k_sfb_cols<136,136, 18496,136, 3*18496,136, 263*136,136><<<grd2(131L*68),256>>>(llB,       yh2,         tmpA);
    k_sfb_cols<136,136, 3*18496,136, 3*18496,136, 263*136,136><<<grd2(131L*68),256>>>(yh2+18496, yh2+2*18496, tmpB);
    k_sfb_rows<262,136, 263*136,136, 263*136,136, 262, 68644,262, 4><<<grdR(262,4),256>>>(tmpA, tmpB, llA);
    // level 1: crop 262->261 -> 512x512 into d_out
    k_sfb_cols<261,261, 68644,262, 3*68644,262, 512*262,262><<<grd2(256L*131),256>>>(llA,       yh1,         tmpA);
    k_sfb_cols<261,261, 3*68644,262, 3*68644,262, 512*262,262><<<grd2(256L*131),256>>>(yh1+68644, yh1+2*68644, tmpB);
    k_sfb_rows<512,261, 512*262,262, 512*262,262, 512, 512*512,512, 2><<<grdR(512,2),256>>>(tmpA, tmpB, out);
}